// round 4
// baseline (speedup 1.0000x reference)
#include <cuda_runtime.h>
#include <cuda_bf16.h>

#define N_NODES   150000
#define N_EDGES   2400000
#define N_FEAT    32
#define N_GRAPHS  8192
#define H1        32
#define H2        64
#define BN_EPS    1e-5f

// ---------------- scratch (static device allocations: allowed) ----------------
__device__ int   d_flag32;              // 1 if edge_index/batch are int32, 0 if int64
__device__ float d_deg[N_NODES];
__device__ float d_isq[N_NODES];
__device__ int   d_batch[N_NODES];
__device__ __align__(16) float d_h1s[N_NODES * H1];   // (x@W1) * isq[row]
__device__ __align__(16) float d_acc1[N_NODES * H1];  // scatter accumulator (init = self loop)
__device__ __align__(16) float d_h2s[N_NODES * H2];   // (z@W2) * isq[row]
__device__ __align__(16) float d_acc2[N_NODES * H2];
__device__ __align__(16) int2  d_edge[N_EDGES];       // packed (src, dst) int32
__device__ float d_stats[64];           // [0:32) sum, [32:64) sumsq of BN input
__device__ float d_A[H1];               // rstd*gamma
__device__ float d_C[H1];               // (b1-mean)*A + beta
__device__ float d_pool[N_GRAPHS * H2];
__device__ float d_cnt[N_GRAPHS];

// ---------------- helpers ----------------
__device__ __forceinline__ void red_add_v4(float* addr, float4 v) {
    unsigned long long g = (unsigned long long)__cvta_generic_to_global(addr);
    asm volatile("red.global.add.v4.f32 [%0], {%1,%2,%3,%4};"
                 :: "l"(g), "f"(v.x), "f"(v.y), "f"(v.z), "f"(v.w)
                 : "memory");
}

// ---------------- kernels ----------------

// Detect index dtype. If the buffer is int32, interpreting it as int64 fuses
// adjacent random indices -> values >= 2^32 (or generally out of range).
__global__ void k_detect(const long long* __restrict__ ei) {
    if (blockIdx.x == 0 && threadIdx.x == 0) {
        int bad = 0;
        for (int i = 0; i < 64; i++) {
            long long v = ei[i];
            if (v < 0 || v >= (long long)N_NODES) bad = 1;
        }
        d_flag32 = bad;
    }
}

// deg = 1 (self loop), zero pool/cnt/stats
__global__ void k_init() {
    int i = blockIdx.x * blockDim.x + threadIdx.x;
    if (i < N_NODES)          d_deg[i] = 1.0f;
    if (i < N_GRAPHS * H2)    d_pool[i] = 0.0f;
    if (i < N_GRAPHS)         d_cnt[i] = 0.0f;
    if (i < 64)               d_stats[i] = 0.0f;
}

// degree count + edge conversion to packed int32 (dtype-agnostic read)
__global__ void k_deg(const void* __restrict__ ei) {
    int e = blockIdx.x * blockDim.x + threadIdx.x;
    if (e < N_EDGES) {
        int s, d;
        if (d_flag32) {
            const int* p = (const int*)ei;
            s = p[e]; d = p[N_EDGES + e];
        } else {
            const long long* p = (const long long*)ei;
            s = (int)p[e]; d = (int)p[N_EDGES + e];
        }
        d_edge[e] = make_int2(s, d);
        atomicAdd(&d_deg[d], 1.0f);
    }
}

// isq + batch conversion + per-graph counts
__global__ void k_isq(const void* __restrict__ batch) {
    int i = blockIdx.x * blockDim.x + threadIdx.x;
    if (i < N_NODES) {
        d_isq[i] = rsqrtf(d_deg[i]);   // deg >= 1 always (self loop)
        int b = d_flag32 ? ((const int*)batch)[i]
                         : (int)((const long long*)batch)[i];
        d_batch[i] = b;
        atomicAdd(&d_cnt[b], 1.0f);
    }
}

// h1s = (x @ W1) * isq ; acc1 = h1s (self-loop contribution)
__global__ void k_gemm1(const float* __restrict__ x, const float* __restrict__ W1) {
    __shared__ float sW[H1 * H1];
    int tid = threadIdx.x;
    for (int i = tid; i < H1 * H1; i += 256) sW[i] = W1[i];
    __syncthreads();
    int warp = tid >> 5, lane = tid & 31;
    int r = blockIdx.x * 8 + warp;
    if (r >= N_NODES) return;
    float xv = x[r * N_FEAT + lane];
    float acc = 0.f;
#pragma unroll
    for (int k = 0; k < 32; k++) {
        float xk = __shfl_sync(0xffffffffu, xv, k);
        acc += xk * sW[k * H1 + lane];
    }
    float v = acc * d_isq[r];
    d_h1s[r * H1 + lane] = v;
    d_acc1[r * H1 + lane] = v;
}

// per-(edge, 16B-chunk) gather + vector red. conv1: 8 chunks of float4 per edge.
__global__ void k_scatter1() {
    int idx = blockIdx.x * blockDim.x + threadIdx.x;
    if (idx >= N_EDGES * 8) return;
    int e = idx >> 3, c = idx & 7;
    int2 ed = d_edge[e];
    float4 v = __ldg(reinterpret_cast<const float4*>(&d_h1s[ed.x * H1 + c * 4]));
    red_add_v4(&d_acc1[ed.y * H1 + c * 4], v);
}

// BN stats over y = acc1*isq + b1 (per feature sum, sumsq)
__global__ void k_bnstats(const float* __restrict__ b1) {
    __shared__ float s_sum[256], s_sq[256];
    int tid = threadIdx.x;
    int f = tid & 31;
    float bf = __ldg(&b1[f]);
    float ls = 0.f, lq = 0.f;
    int stride = gridDim.x * blockDim.x;          // multiple of 32 -> f invariant
    for (int i = blockIdx.x * blockDim.x + tid; i < N_NODES * H1; i += stride) {
        int row = i >> 5;
        float y = d_acc1[i] * d_isq[row] + bf;
        ls += y;
        lq += y * y;
    }
    s_sum[tid] = ls; s_sq[tid] = lq;
    __syncthreads();
    if (tid < 32) {
        float ts = s_sum[tid], tq = s_sq[tid];
#pragma unroll
        for (int g = 1; g < 8; g++) { ts += s_sum[tid + 32 * g]; tq += s_sq[tid + 32 * g]; }
        atomicAdd(&d_stats[tid], ts);
        atomicAdd(&d_stats[32 + tid], tq);
    }
}

__global__ void k_bnfinal(const float* __restrict__ b1,
                          const float* __restrict__ gamma,
                          const float* __restrict__ beta) {
    int f = threadIdx.x;
    float n = (float)N_NODES;
    float mean = d_stats[f] / n;
    float var = d_stats[32 + f] / n - mean * mean;
    float A = rsqrtf(var + BN_EPS) * gamma[f];
    d_A[f] = A;
    d_C[f] = (b1[f] - mean) * A + beta[f];
}

// z = relu(acc1*isq*A + C); h2s = (z @ W2) * isq; acc2 = h2s
__global__ void k_gemm2(const float* __restrict__ W2) {
    __shared__ float sW[H1 * H2];
    int tid = threadIdx.x;
    for (int i = tid; i < H1 * H2; i += 256) sW[i] = W2[i];
    __syncthreads();
    int warp = tid >> 5, lane = tid & 31;
    int r = blockIdx.x * 8 + warp;
    if (r >= N_NODES) return;
    float isq = d_isq[r];
    float z = fmaxf(d_acc1[r * H1 + lane] * isq * d_A[lane] + d_C[lane], 0.0f);
    float o0 = 0.f, o1 = 0.f;
#pragma unroll
    for (int k = 0; k < 32; k++) {
        float zk = __shfl_sync(0xffffffffu, z, k);
        o0 += zk * sW[k * H2 + lane];
        o1 += zk * sW[k * H2 + lane + 32];
    }
    o0 *= isq; o1 *= isq;
    d_h2s[r * H2 + lane]        = o0;
    d_h2s[r * H2 + lane + 32]   = o1;
    d_acc2[r * H2 + lane]       = o0;
    d_acc2[r * H2 + lane + 32]  = o1;
}

// conv2: 16 chunks of float4 per edge
__global__ void k_scatter2() {
    int idx = blockIdx.x * blockDim.x + threadIdx.x;
    if (idx >= N_EDGES * 16) return;
    int e = idx >> 4, c = idx & 15;
    int2 ed = d_edge[e];
    float4 v = __ldg(reinterpret_cast<const float4*>(&d_h2s[ed.x * H2 + c * 4]));
    red_add_v4(&d_acc2[ed.y * H2 + c * 4], v);
}

// mean-pool: sums += acc2*isq + b2
__global__ void k_pool(const float* __restrict__ b2) {
    int idx = blockIdx.x * blockDim.x + threadIdx.x;
    if (idx >= N_NODES * H2) return;
    int node = idx >> 6, f = idx & 63;
    int b = d_batch[node];
    float v = d_acc2[idx] * d_isq[node] + __ldg(&b2[f]);
    atomicAdd(&d_pool[b * H2 + f], v);
}

// warp-per-graph MLP head: g -> relu(g@Wfc1+bfc1) -> @Wfc2+bfc2 -> (mu, log_sigma)
__global__ void __launch_bounds__(1024) k_mlp(const float* __restrict__ Wfc1,
                                              const float* __restrict__ bfc1,
                                              const float* __restrict__ Wfc2,
                                              const float* __restrict__ bfc2,
                                              float* __restrict__ out) {
    __shared__ float sW1[64 * 128];
    __shared__ float sb1[128];
    int tid = threadIdx.x;
    for (int i = tid; i < 64 * 128; i += 1024) sW1[i] = Wfc1[i];
    if (tid < 128) sb1[tid] = bfc1[tid];
    __syncthreads();
    int warp = tid >> 5, lane = tid & 31;
    int g = blockIdx.x * 32 + warp;
    float inv = 1.0f / fmaxf(d_cnt[g], 1.0f);
    float g0 = d_pool[g * H2 + lane] * inv;
    float g1 = d_pool[g * H2 + 32 + lane] * inv;
    float a0 = 0.f, a1 = 0.f, a2 = 0.f, a3 = 0.f;
#pragma unroll
    for (int k = 0; k < 32; k++) {
        float gk = __shfl_sync(0xffffffffu, g0, k);
        const float* w = &sW1[k * 128];
        a0 += gk * w[lane]; a1 += gk * w[lane + 32]; a2 += gk * w[lane + 64]; a3 += gk * w[lane + 96];
    }
#pragma unroll
    for (int k = 0; k < 32; k++) {
        float gk = __shfl_sync(0xffffffffu, g1, k);
        const float* w = &sW1[(k + 32) * 128];
        a0 += gk * w[lane]; a1 += gk * w[lane + 32]; a2 += gk * w[lane + 64]; a3 += gk * w[lane + 96];
    }
    float h0 = fmaxf(a0 + sb1[lane], 0.f);
    float h1 = fmaxf(a1 + sb1[lane + 32], 0.f);
    float h2 = fmaxf(a2 + sb1[lane + 64], 0.f);
    float h3 = fmaxf(a3 + sb1[lane + 96], 0.f);

    float o0 = __ldg(&bfc2[lane]);
    float o1 = __ldg(&bfc2[lane + 32]);
    float o2 = __ldg(&bfc2[lane + 64]);
    float o3 = __ldg(&bfc2[lane + 96]);
#pragma unroll
    for (int k = 0; k < 32; k++) {
        float hk = __shfl_sync(0xffffffffu, h0, k);
        const float* w = &Wfc2[k * 128];
        o0 += hk * __ldg(&w[lane]); o1 += hk * __ldg(&w[lane + 32]);
        o2 += hk * __ldg(&w[lane + 64]); o3 += hk * __ldg(&w[lane + 96]);
    }
#pragma unroll
    for (int k = 0; k < 32; k++) {
        float hk = __shfl_sync(0xffffffffu, h1, k);
        const float* w = &Wfc2[(k + 32) * 128];
        o0 += hk * __ldg(&w[lane]); o1 += hk * __ldg(&w[lane + 32]);
        o2 += hk * __ldg(&w[lane + 64]); o3 += hk * __ldg(&w[lane + 96]);
    }
#pragma unroll
    for (int k = 0; k < 32; k++) {
        float hk = __shfl_sync(0xffffffffu, h2, k);
        const float* w = &Wfc2[(k + 64) * 128];
        o0 += hk * __ldg(&w[lane]); o1 += hk * __ldg(&w[lane + 32]);
        o2 += hk * __ldg(&w[lane + 64]); o3 += hk * __ldg(&w[lane + 96]);
    }
#pragma unroll
    for (int k = 0; k < 32; k++) {
        float hk = __shfl_sync(0xffffffffu, h3, k);
        const float* w = &Wfc2[(k + 96) * 128];
        o0 += hk * __ldg(&w[lane]); o1 += hk * __ldg(&w[lane + 32]);
        o2 += hk * __ldg(&w[lane + 64]); o3 += hk * __ldg(&w[lane + 96]);
    }
    // cols 0..63 -> mu, 64..127 -> log_sigma (concatenated output)
    out[g * 64 + lane]                      = o0;
    out[g * 64 + lane + 32]                 = o1;
    out[N_GRAPHS * 64 + g * 64 + lane]      = o2;
    out[N_GRAPHS * 64 + g * 64 + lane + 32] = o3;
}

// ---------------- launch ----------------
extern "C" void kernel_launch(void* const* d_in, const int* in_sizes, int n_in,
                              void* d_out, int out_size) {
    const float* x     = (const float*)d_in[0];
    const void*  ei    = d_in[1];                 // [2, N_EDGES], int32 or int64
    const void*  batch = d_in[2];                 // [N_NODES], int32 or int64
    const float* W1    = (const float*)d_in[3];
    const float* b1    = (const float*)d_in[4];
    const float* gamma = (const float*)d_in[5];
    const float* beta  = (const float*)d_in[6];
    const float* W2    = (const float*)d_in[7];
    const float* b2    = (const float*)d_in[8];
    const float* Wfc1  = (const float*)d_in[9];
    const float* bfc1  = (const float*)d_in[10];
    const float* Wfc2  = (const float*)d_in[11];
    const float* bfc2  = (const float*)d_in[12];
    float* out = (float*)d_out;

    k_detect<<<1, 32>>>((const long long*)ei);
    k_init<<<(N_GRAPHS * H2 + 255) / 256 + 1, 256>>>();
    k_deg<<<(N_EDGES + 255) / 256, 256>>>(ei);
    k_isq<<<(N_NODES + 255) / 256, 256>>>(batch);
    k_gemm1<<<(N_NODES + 7) / 8, 256>>>(x, W1);
    k_scatter1<<<(N_EDGES * 8 + 255) / 256, 256>>>();
    k_bnstats<<<1024, 256>>>(b1);
    k_bnfinal<<<1, 32>>>(b1, gamma, beta);
    k_gemm2<<<(N_NODES + 7) / 8, 256>>>(W2);
    k_scatter2<<<(N_EDGES * 16 + 255) / 256, 256>>>();
    k_pool<<<(N_NODES * H2 + 255) / 256, 256>>>(b2);
    k_mlp<<<N_GRAPHS / 32, 1024>>>(Wfc1, bfc1, Wfc2, bfc2, out);
}

// round 5
// speedup vs baseline: 1.5211x; 1.5211x over previous
#include <cuda_runtime.h>
#include <cuda_bf16.h>

#define N_NODES   150000
#define N_EDGES   2400000
#define N_FEAT    32
#define N_GRAPHS  8192
#define H1        32
#define H2        64
#define BN_EPS    1e-5f

// ---------------- scratch (static device allocations: allowed) ----------------
__device__ int   d_flag32;              // 1 if edge_index/batch are int32, 0 if int64
__device__ float d_deg[N_NODES];
__device__ float d_isq[N_NODES];
__device__ int   d_batch[N_NODES];
__device__ __align__(16) float d_h1s[N_NODES * H1];   // (x@W1) * isq[row]
__device__ __align__(16) float d_acc1[N_NODES * H1];  // conv1 accumulator (init = self loop)
__device__ __align__(16) float d_zs[N_NODES * H1];    // relu(BN(h1)) * isq  (conv2 message, 32-dim)
__device__ __align__(16) float d_accz[N_NODES * H1];  // conv2 accumulator (32-dim, pre-W2)
__device__ __align__(16) int2  d_edge[N_EDGES];       // packed (src, dst) int32
__device__ float d_stats[64];           // [0:32) sum, [32:64) sumsq of BN input
__device__ float d_A[H1];               // rstd*gamma
__device__ float d_C[H1];               // (b1-mean)*A + beta
__device__ __align__(16) float d_poolz[N_GRAPHS * H1];  // 32-dim pooled pre-W2 sums
__device__ float d_cnt[N_GRAPHS];

// ---------------- helpers ----------------
__device__ __forceinline__ void red_add_v4(float* addr, float4 v) {
    unsigned long long g = (unsigned long long)__cvta_generic_to_global(addr);
    asm volatile("red.global.add.v4.f32 [%0], {%1,%2,%3,%4};"
                 :: "l"(g), "f"(v.x), "f"(v.y), "f"(v.z), "f"(v.w)
                 : "memory");
}

// ---------------- kernels ----------------

// Detect index dtype (int32 vs int64) from value range.
__global__ void k_detect(const long long* __restrict__ ei) {
    if (blockIdx.x == 0 && threadIdx.x == 0) {
        int bad = 0;
        for (int i = 0; i < 64; i++) {
            long long v = ei[i];
            if (v < 0 || v >= (long long)N_NODES) bad = 1;
        }
        d_flag32 = bad;
    }
}

// deg = 1 (self loop), zero poolz/cnt/stats
__global__ void k_init() {
    int i = blockIdx.x * blockDim.x + threadIdx.x;
    if (i < N_NODES)          d_deg[i] = 1.0f;
    if (i < N_GRAPHS * H1)    d_poolz[i] = 0.0f;
    if (i < N_GRAPHS)         d_cnt[i] = 0.0f;
    if (i < 64)               d_stats[i] = 0.0f;
}

// degree count + edge conversion to packed int32 (dtype-agnostic read)
__global__ void k_deg(const void* __restrict__ ei) {
    int e = blockIdx.x * blockDim.x + threadIdx.x;
    if (e < N_EDGES) {
        int s, d;
        if (d_flag32) {
            const int* p = (const int*)ei;
            s = p[e]; d = p[N_EDGES + e];
        } else {
            const long long* p = (const long long*)ei;
            s = (int)p[e]; d = (int)p[N_EDGES + e];
        }
        d_edge[e] = make_int2(s, d);
        atomicAdd(&d_deg[d], 1.0f);
    }
}

// isq + batch conversion + per-graph counts
__global__ void k_isq(const void* __restrict__ batch) {
    int i = blockIdx.x * blockDim.x + threadIdx.x;
    if (i < N_NODES) {
        d_isq[i] = rsqrtf(d_deg[i]);   // deg >= 1 always (self loop)
        int b = d_flag32 ? ((const int*)batch)[i]
                         : (int)((const long long*)batch)[i];
        d_batch[i] = b;
        atomicAdd(&d_cnt[b], 1.0f);
    }
}

// h1s = (x @ W1) * isq ; acc1 = h1s (self-loop contribution)
__global__ void k_gemm1(const float* __restrict__ x, const float* __restrict__ W1) {
    __shared__ float sW[H1 * H1];
    int tid = threadIdx.x;
    for (int i = tid; i < H1 * H1; i += 256) sW[i] = W1[i];
    __syncthreads();
    int warp = tid >> 5, lane = tid & 31;
    int r = blockIdx.x * 8 + warp;
    if (r >= N_NODES) return;
    float xv = x[r * N_FEAT + lane];
    float acc = 0.f;
#pragma unroll
    for (int k = 0; k < 32; k++) {
        float xk = __shfl_sync(0xffffffffu, xv, k);
        acc += xk * sW[k * H1 + lane];
    }
    float v = acc * d_isq[r];
    d_h1s[r * H1 + lane] = v;
    d_acc1[r * H1 + lane] = v;
}

// conv1 scatter: per-(edge, 16B-chunk), 8 chunks of float4 per edge.
__global__ void k_scatter1() {
    int idx = blockIdx.x * blockDim.x + threadIdx.x;
    if (idx >= N_EDGES * 8) return;
    int e = idx >> 3, c = idx & 7;
    int2 ed = d_edge[e];
    float4 v = __ldg(reinterpret_cast<const float4*>(&d_h1s[ed.x * H1 + c * 4]));
    red_add_v4(&d_acc1[ed.y * H1 + c * 4], v);
}

// BN stats over y = acc1*isq + b1 (per feature sum, sumsq)
__global__ void k_bnstats(const float* __restrict__ b1) {
    __shared__ float s_sum[256], s_sq[256];
    int tid = threadIdx.x;
    int f = tid & 31;
    float bf = __ldg(&b1[f]);
    float ls = 0.f, lq = 0.f;
    int stride = gridDim.x * blockDim.x;          // multiple of 32 -> f invariant
    for (int i = blockIdx.x * blockDim.x + tid; i < N_NODES * H1; i += stride) {
        int row = i >> 5;
        float y = d_acc1[i] * d_isq[row] + bf;
        ls += y;
        lq += y * y;
    }
    s_sum[tid] = ls; s_sq[tid] = lq;
    __syncthreads();
    if (tid < 32) {
        float ts = s_sum[tid], tq = s_sq[tid];
#pragma unroll
        for (int g = 1; g < 8; g++) { ts += s_sum[tid + 32 * g]; tq += s_sq[tid + 32 * g]; }
        atomicAdd(&d_stats[tid], ts);
        atomicAdd(&d_stats[32 + tid], tq);
    }
}

__global__ void k_bnfinal(const float* __restrict__ b1,
                          const float* __restrict__ gamma,
                          const float* __restrict__ beta) {
    int f = threadIdx.x;
    float n = (float)N_NODES;
    float mean = d_stats[f] / n;
    float var = d_stats[32 + f] / n - mean * mean;
    float A = rsqrtf(var + BN_EPS) * gamma[f];
    d_A[f] = A;
    d_C[f] = (b1[f] - mean) * A + beta[f];
}

// zs = relu(acc1*isq*A + C) * isq ; accz = zs (self-loop contribution)
__global__ void k_zs() {
    int i = blockIdx.x * blockDim.x + threadIdx.x;
    if (i >= N_NODES * H1) return;
    int row = i >> 5, f = i & 31;
    float isq = d_isq[row];
    float z = fmaxf(d_acc1[i] * isq * d_A[f] + d_C[f], 0.0f);
    float v = z * isq;
    d_zs[i] = v;
    d_accz[i] = v;
}

// conv2 scatter (pre-W2, 32-dim): 8 chunks of float4 per edge.
__global__ void k_scatter2() {
    int idx = blockIdx.x * blockDim.x + threadIdx.x;
    if (idx >= N_EDGES * 8) return;
    int e = idx >> 3, c = idx & 7;
    int2 ed = d_edge[e];
    float4 v = __ldg(reinterpret_cast<const float4*>(&d_zs[ed.x * H1 + c * 4]));
    red_add_v4(&d_accz[ed.y * H1 + c * 4], v);
}

// mean-pool (pre-W2): poolz[b] += accz[node]*isq[node]  (32 floats per node)
__global__ void k_pool() {
    int idx = blockIdx.x * blockDim.x + threadIdx.x;
    if (idx >= N_NODES * 8) return;
    int node = idx >> 3, c = idx & 7;
    int b = d_batch[node];
    float isq = d_isq[node];
    float4 v = *reinterpret_cast<const float4*>(&d_accz[node * H1 + c * 4]);
    v.x *= isq; v.y *= isq; v.z *= isq; v.w *= isq;
    red_add_v4(&d_poolz[b * H1 + c * 4], v);
}

// warp-per-graph head: g64 = (poolz@W2 + cnt*b2)/max(cnt,1); relu(g@Wfc1+bfc1); @Wfc2+bfc2
__global__ void __launch_bounds__(1024) k_mlp(const float* __restrict__ W2,
                                              const float* __restrict__ b2,
                                              const float* __restrict__ Wfc1,
                                              const float* __restrict__ bfc1,
                                              const float* __restrict__ Wfc2,
                                              const float* __restrict__ bfc2,
                                              float* __restrict__ out) {
    __shared__ float sW2[H1 * H2];     // 32x64
    __shared__ float sW1[64 * 128];
    __shared__ float sb1[128];
    __shared__ float sb2[64];
    int tid = threadIdx.x;
    for (int i = tid; i < H1 * H2; i += 1024) sW2[i] = W2[i];
    for (int i = tid; i < 64 * 128; i += 1024) sW1[i] = Wfc1[i];
    if (tid < 128) sb1[tid] = bfc1[tid];
    if (tid < 64)  sb2[tid] = b2[tid];
    __syncthreads();
    int warp = tid >> 5, lane = tid & 31;
    int g = blockIdx.x * 32 + warp;
    float cnt = d_cnt[g];
    float inv = 1.0f / fmaxf(cnt, 1.0f);
    float p = d_poolz[g * H1 + lane];
    float e0 = 0.f, e1 = 0.f;
#pragma unroll
    for (int k = 0; k < 32; k++) {
        float pk = __shfl_sync(0xffffffffu, p, k);
        e0 += pk * sW2[k * H2 + lane];
        e1 += pk * sW2[k * H2 + lane + 32];
    }
    float g0 = (e0 + cnt * sb2[lane]) * inv;
    float g1 = (e1 + cnt * sb2[lane + 32]) * inv;

    float a0 = 0.f, a1 = 0.f, a2 = 0.f, a3 = 0.f;
#pragma unroll
    for (int k = 0; k < 32; k++) {
        float gk = __shfl_sync(0xffffffffu, g0, k);
        const float* w = &sW1[k * 128];
        a0 += gk * w[lane]; a1 += gk * w[lane + 32]; a2 += gk * w[lane + 64]; a3 += gk * w[lane + 96];
    }
#pragma unroll
    for (int k = 0; k < 32; k++) {
        float gk = __shfl_sync(0xffffffffu, g1, k);
        const float* w = &sW1[(k + 32) * 128];
        a0 += gk * w[lane]; a1 += gk * w[lane + 32]; a2 += gk * w[lane + 64]; a3 += gk * w[lane + 96];
    }
    float h0 = fmaxf(a0 + sb1[lane], 0.f);
    float h1 = fmaxf(a1 + sb1[lane + 32], 0.f);
    float h2 = fmaxf(a2 + sb1[lane + 64], 0.f);
    float h3 = fmaxf(a3 + sb1[lane + 96], 0.f);

    float o0 = __ldg(&bfc2[lane]);
    float o1 = __ldg(&bfc2[lane + 32]);
    float o2 = __ldg(&bfc2[lane + 64]);
    float o3 = __ldg(&bfc2[lane + 96]);
#pragma unroll
    for (int k = 0; k < 32; k++) {
        float hk = __shfl_sync(0xffffffffu, h0, k);
        const float* w = &Wfc2[k * 128];
        o0 += hk * __ldg(&w[lane]); o1 += hk * __ldg(&w[lane + 32]);
        o2 += hk * __ldg(&w[lane + 64]); o3 += hk * __ldg(&w[lane + 96]);
    }
#pragma unroll
    for (int k = 0; k < 32; k++) {
        float hk = __shfl_sync(0xffffffffu, h1, k);
        const float* w = &Wfc2[(k + 32) * 128];
        o0 += hk * __ldg(&w[lane]); o1 += hk * __ldg(&w[lane + 32]);
        o2 += hk * __ldg(&w[lane + 64]); o3 += hk * __ldg(&w[lane + 96]);
    }
#pragma unroll
    for (int k = 0; k < 32; k++) {
        float hk = __shfl_sync(0xffffffffu, h2, k);
        const float* w = &Wfc2[(k + 64) * 128];
        o0 += hk * __ldg(&w[lane]); o1 += hk * __ldg(&w[lane + 32]);
        o2 += hk * __ldg(&w[lane + 64]); o3 += hk * __ldg(&w[lane + 96]);
    }
#pragma unroll
    for (int k = 0; k < 32; k++) {
        float hk = __shfl_sync(0xffffffffu, h3, k);
        const float* w = &Wfc2[(k + 96) * 128];
        o0 += hk * __ldg(&w[lane]); o1 += hk * __ldg(&w[lane + 32]);
        o2 += hk * __ldg(&w[lane + 64]); o3 += hk * __ldg(&w[lane + 96]);
    }
    // cols 0..63 -> mu, 64..127 -> log_sigma (concatenated output)
    out[g * 64 + lane]                      = o0;
    out[g * 64 + lane + 32]                 = o1;
    out[N_GRAPHS * 64 + g * 64 + lane]      = o2;
    out[N_GRAPHS * 64 + g * 64 + lane + 32] = o3;
}

// ---------------- launch ----------------
extern "C" void kernel_launch(void* const* d_in, const int* in_sizes, int n_in,
                              void* d_out, int out_size) {
    const float* x     = (const float*)d_in[0];
    const void*  ei    = d_in[1];                 // [2, N_EDGES], int32 or int64
    const void*  batch = d_in[2];                 // [N_NODES], int32 or int64
    const float* W1    = (const float*)d_in[3];
    const float* b1    = (const float*)d_in[4];
    const float* gamma = (const float*)d_in[5];
    const float* beta  = (const float*)d_in[6];
    const float* W2    = (const float*)d_in[7];
    const float* b2    = (const float*)d_in[8];
    const float* Wfc1  = (const float*)d_in[9];
    const float* bfc1  = (const float*)d_in[10];
    const float* Wfc2  = (const float*)d_in[11];
    const float* bfc2  = (const float*)d_in[12];
    float* out = (float*)d_out;

    k_detect<<<1, 32>>>((const long long*)ei);
    k_init<<<(N_GRAPHS * H1 + 255) / 256, 256>>>();
    k_deg<<<(N_EDGES + 255) / 256, 256>>>(ei);
    k_isq<<<(N_NODES + 255) / 256, 256>>>(batch);
    k_gemm1<<<(N_NODES + 7) / 8, 256>>>(x, W1);
    k_scatter1<<<(N_EDGES * 8 + 255) / 256, 256>>>();
    k_bnstats<<<1024, 256>>>(b1);
    k_bnfinal<<<1, 32>>>(b1, gamma, beta);
    k_zs<<<(N_NODES * H1 + 255) / 256, 256>>>();
    k_scatter2<<<(N_EDGES * 8 + 255) / 256, 256>>>();
    k_pool<<<(N_NODES * 8 + 255) / 256, 256>>>();
    k_mlp<<<N_GRAPHS / 32, 1024>>>(W2, b2, Wfc1, bfc1, Wfc2, bfc2, out);
}